// round 14
// baseline (speedup 1.0000x reference)
#include <cuda_runtime.h>
#include <cstdint>

// Problem constants (fixed shapes from reference setup_inputs):
// x:      (B=4, C=32, H=256, W=256) fp32
// kernel: (B=4, C*K*K=800, H=256, W=256) fp32, channel = c*25 + i*5 + j
// out:    same shape as x
// out[b,c,y,x] = sum_{i,j} x_edgepad[b,c,y+i-2,x+j-2] * kernel[b,(c*5+i)*5+j,y,x]

constexpr int H  = 256;
constexpr int W  = 256;
constexpr int HW = H * W;
constexpr int KK = 25;

// Block: 512 threads, one (b,c) slice, 16 consecutive output rows
// (two sequential 8-row passes reusing the same registers).
// Each thread produces 4 consecutive outputs along x (float4) per pass.
// Shared tile: 20 x-rows (16 output rows + 2 halo each side), cols:
//   [0,1]     = left edge replication (global col 0)
//   [2..257]  = global cols 0..255
//   [258,259] = right edge replication (global col 255)
// Row padded to 264 floats (1056 B, 16B-aligned row base) so compute-side
// float4 reads at column x0 (x0 % 4 == 0) are 16B-aligned. Interior staging
// stores land at byte offset 8 mod 16 -> two float2 stores (8B-aligned).
//
// NOTE: no register cap. R9 showed that forcing 32 regs (4 CTAs/SM, 90% occ)
// serializes the 5-wide LDG.128 tap batch and LOSES bandwidth (85.3% vs
// 88.3% DRAM). Per-warp MLP > occupancy for this stream.
__global__ void __launch_bounds__(512)
kpconv_kernel(const float* __restrict__ x,
              const float* __restrict__ kern,
              float* __restrict__ out)
{
    __shared__ __align__(16) float s[20][264];

    const int yg = blockIdx.x;            // 0..15  (row group of 16)
    const int bc = blockIdx.y;            // 0..127 (b*C + c)
    const int y0 = yg << 4;               // first output row of this block
    const int t  = threadIdx.x;

    const float* xsl = x + (size_t)bc * HW;   // this (b,c) slice of x

    // ---- Stage x tile into shared memory (with edge replication) ----
    // Interior: 20 rows * 64 float4 = 1280 vector loads over 512 threads.
    {
        #pragma unroll
        for (int rep = 0; rep < 3; ++rep) {
            int idx = t + rep * 512;
            if (idx < 20 * 64) {
                int sy = idx >> 6;                       // 0..19
                int q  = idx & 63;                       // 0..63
                int gy = y0 + sy - 2;
                gy = gy < 0 ? 0 : (gy > H - 1 ? H - 1 : gy);
                float4 v = __ldg((const float4*)(xsl + gy * W + (q << 2)));
                float* dst = &s[sy][2 + (q << 2)];
                *(float2*)(dst)     = make_float2(v.x, v.y);
                *(float2*)(dst + 2) = make_float2(v.z, v.w);
            }
        }
        // Horizontal edge replication: 4 scalars per row, 80 total.
        if (t < 80) {
            int sy = t >> 2;                             // 0..19
            int e  = t & 3;
            int gy = y0 + sy - 2;
            gy = gy < 0 ? 0 : (gy > H - 1 ? H - 1 : gy);
            if (e < 2) s[sy][e]           = xsl[gy * W];          // cols -2,-1
            else       s[sy][258 + (e-2)] = xsl[gy * W + W - 1];  // cols 256,257
        }
    }
    __syncthreads();

    // ---- Compute: two sequential 8-row passes, 4 outputs/thread each ----
    const int ry = t >> 6;                 // 0..7  output row within pass
    const int x0 = (t & 63) << 2;          // 0..252 output col (float4 aligned)

    #pragma unroll
    for (int p = 0; p < 2; ++p) {
        const int yloc = p * 8 + ry;       // row within 16-row group
        const int y    = y0 + yloc;        // global output row

        // Kernel tap base: taps are base + tap*HW (tap*256KB byte offsets).
        const float* kb = kern + (size_t)bc * KK * HW + (size_t)y * W + x0;

        float4 acc = make_float4(0.f, 0.f, 0.f, 0.f);

        #pragma unroll
        for (int i = 0; i < 5; ++i) {
            // x window: smem cols x0 .. x0+7 of row (yloc+i). 16B-aligned.
            const float4 a = *(const float4*)&s[yloc + i][x0];
            const float4 b = *(const float4*)&s[yloc + i][x0 + 4];

            // Streaming loads: kernel tensor has zero reuse, keep it from
            // evicting the x slices in L2. 5 independent LDG.128 batched.
            const float4 w0 = __ldcs((const float4*)(kb + (i * 5 + 0) * HW));
            const float4 w1 = __ldcs((const float4*)(kb + (i * 5 + 1) * HW));
            const float4 w2 = __ldcs((const float4*)(kb + (i * 5 + 2) * HW));
            const float4 w3 = __ldcs((const float4*)(kb + (i * 5 + 3) * HW));
            const float4 w4 = __ldcs((const float4*)(kb + (i * 5 + 4) * HW));

            // j = 0: window a.x..a.w
            acc.x = fmaf(a.x, w0.x, acc.x);
            acc.y = fmaf(a.y, w0.y, acc.y);
            acc.z = fmaf(a.z, w0.z, acc.z);
            acc.w = fmaf(a.w, w0.w, acc.w);
            // j = 1: a.y..b.x
            acc.x = fmaf(a.y, w1.x, acc.x);
            acc.y = fmaf(a.z, w1.y, acc.y);
            acc.z = fmaf(a.w, w1.z, acc.z);
            acc.w = fmaf(b.x, w1.w, acc.w);
            // j = 2: a.z..b.y
            acc.x = fmaf(a.z, w2.x, acc.x);
            acc.y = fmaf(a.w, w2.y, acc.y);
            acc.z = fmaf(b.x, w2.z, acc.z);
            acc.w = fmaf(b.y, w2.w, acc.w);
            // j = 3: a.w..b.z
            acc.x = fmaf(a.w, w3.x, acc.x);
            acc.y = fmaf(b.x, w3.y, acc.y);
            acc.z = fmaf(b.y, w3.z, acc.z);
            acc.w = fmaf(b.z, w3.w, acc.w);
            // j = 4: b.x..b.w
            acc.x = fmaf(b.x, w4.x, acc.x);
            acc.y = fmaf(b.y, w4.y, acc.y);
            acc.z = fmaf(b.z, w4.z, acc.z);
            acc.w = fmaf(b.w, w4.w, acc.w);
        }

        __stcs((float4*)(out + (size_t)bc * HW + (size_t)y * W + x0), acc);
    }
}

extern "C" void kernel_launch(void* const* d_in, const int* in_sizes, int n_in,
                              void* d_out, int out_size)
{
    const float* x    = (const float*)d_in[0];   // (4,32,256,256)
    const float* kern = (const float*)d_in[1];   // (4,800,256,256)
    // d_in[2] = kernel_size (int scalar) — fixed at 5, compiled in.
    float* out = (float*)d_out;

    dim3 grid(H / 16, 4 * 32);   // 16 row-groups x 128 (b,c) slices
    kpconv_kernel<<<grid, 512>>>(x, kern, out);
}

// round 15
// speedup vs baseline: 1.0219x; 1.0219x over previous
#include <cuda_runtime.h>
#include <cstdint>

// Problem constants (fixed shapes from reference setup_inputs):
// x:      (B=4, C=32, H=256, W=256) fp32
// kernel: (B=4, C*K*K=800, H=256, W=256) fp32, channel = c*25 + i*5 + j
// out:    same shape as x
// out[b,c,y,x] = sum_{i,j} x_edgepad[b,c,y+i-2,x+j-2] * kernel[b,(c*5+i)*5+j,y,x]
//
// Workload is a pure HBM stream: kernel tensor (839 MB) read once with zero
// reuse dominates. Best operating point (empirically bracketed):
//   rows/CTA {4:125.1us, 8:123.4us, 16:125.7us}  -> 8
//   regs {32-forced:129.5us, 38-natural:123.4us} -> natural (per-warp MLP
//        of the 5-wide LDG.128 tap batch beats occupancy)
// Traffic is at the compulsory minimum (~879 MB); DRAM at ~88.7% of spec is
// the mixed read/write stream ceiling.

constexpr int H  = 256;
constexpr int W  = 256;
constexpr int HW = H * W;
constexpr int KK = 25;

// Block: 512 threads, one (b,c) slice, 8 consecutive output rows.
// Each thread produces 4 consecutive outputs along x (float4).
// Shared tile: 12 x-rows (8 output rows + 2 halo each side), cols:
//   [0,1]     = left edge replication (global col 0)
//   [2..257]  = global cols 0..255
//   [258,259] = right edge replication (global col 255)
// Row padded to 264 floats (1056 B, 16B-aligned row base) so compute-side
// float4 reads at column x0 (x0 % 4 == 0) are 16B-aligned. Interior staging
// stores land at byte offset 8 mod 16 -> two float2 stores (8B-aligned).
__global__ void __launch_bounds__(512)
kpconv_kernel(const float* __restrict__ x,
              const float* __restrict__ kern,
              float* __restrict__ out)
{
    __shared__ __align__(16) float s[12][264];

    const int yg = blockIdx.x;            // 0..31  (row group)
    const int bc = blockIdx.y;            // 0..127 (b*C + c)
    const int y0 = yg << 3;               // first output row of this block
    const int t  = threadIdx.x;

    const float* xsl = x + (size_t)bc * HW;   // this (b,c) slice of x

    // ---- Stage x tile into shared memory (with edge replication) ----
    // Interior: 12 rows * 64 float4 = 768 vector loads over 512 threads.
    {
        #pragma unroll
        for (int rep = 0; rep < 2; ++rep) {
            int idx = t + rep * 512;
            if (idx < 12 * 64) {
                int sy = idx >> 6;                       // 0..11
                int q  = idx & 63;                       // 0..63
                int gy = y0 + sy - 2;
                gy = gy < 0 ? 0 : (gy > H - 1 ? H - 1 : gy);
                float4 v = __ldg((const float4*)(xsl + gy * W + (q << 2)));
                float* dst = &s[sy][2 + (q << 2)];
                *(float2*)(dst)     = make_float2(v.x, v.y);
                *(float2*)(dst + 2) = make_float2(v.z, v.w);
            }
        }
        // Horizontal edge replication: 4 scalars per row, 48 total.
        if (t < 48) {
            int sy = t >> 2;                             // 0..11
            int e  = t & 3;
            int gy = y0 + sy - 2;
            gy = gy < 0 ? 0 : (gy > H - 1 ? H - 1 : gy);
            if (e < 2) s[sy][e]           = xsl[gy * W];          // cols -2,-1
            else       s[sy][258 + (e-2)] = xsl[gy * W + W - 1];  // cols 256,257
        }
    }
    __syncthreads();

    // ---- Compute 4 outputs per thread ----
    const int ry = t >> 6;                 // 0..7  output row within group
    const int x0 = (t & 63) << 2;          // 0..252 output col (float4 aligned)
    const int y  = y0 + ry;

    // Kernel tap base: taps are base + tap*HW (tap*256KB byte offsets).
    const float* kb = kern + (size_t)bc * KK * HW + (size_t)y * W + x0;

    float4 acc = make_float4(0.f, 0.f, 0.f, 0.f);

    #pragma unroll
    for (int i = 0; i < 5; ++i) {
        // x window for output cols x0..x0+3, taps j=0..4:
        // needs smem cols x0 .. x0+7 of row (ry+i). Both reads 16B-aligned.
        const float4 a = *(const float4*)&s[ry + i][x0];
        const float4 b = *(const float4*)&s[ry + i][x0 + 4];

        // Streaming loads: kernel tensor has zero reuse, keep it from
        // evicting the x slices in L2. 5 independent LDG.128 per iteration,
        // front-batched for MLP.
        const float4 w0 = __ldcs((const float4*)(kb + (i * 5 + 0) * HW));
        const float4 w1 = __ldcs((const float4*)(kb + (i * 5 + 1) * HW));
        const float4 w2 = __ldcs((const float4*)(kb + (i * 5 + 2) * HW));
        const float4 w3 = __ldcs((const float4*)(kb + (i * 5 + 3) * HW));
        const float4 w4 = __ldcs((const float4*)(kb + (i * 5 + 4) * HW));

        // j = 0: window a.x..a.w
        acc.x = fmaf(a.x, w0.x, acc.x);
        acc.y = fmaf(a.y, w0.y, acc.y);
        acc.z = fmaf(a.z, w0.z, acc.z);
        acc.w = fmaf(a.w, w0.w, acc.w);
        // j = 1: a.y..b.x
        acc.x = fmaf(a.y, w1.x, acc.x);
        acc.y = fmaf(a.z, w1.y, acc.y);
        acc.z = fmaf(a.w, w1.z, acc.z);
        acc.w = fmaf(b.x, w1.w, acc.w);
        // j = 2: a.z..b.y
        acc.x = fmaf(a.z, w2.x, acc.x);
        acc.y = fmaf(a.w, w2.y, acc.y);
        acc.z = fmaf(b.x, w2.z, acc.z);
        acc.w = fmaf(b.y, w2.w, acc.w);
        // j = 3: a.w..b.z
        acc.x = fmaf(a.w, w3.x, acc.x);
        acc.y = fmaf(b.x, w3.y, acc.y);
        acc.z = fmaf(b.y, w3.z, acc.z);
        acc.w = fmaf(b.z, w3.w, acc.w);
        // j = 4: b.x..b.w
        acc.x = fmaf(b.x, w4.x, acc.x);
        acc.y = fmaf(b.y, w4.y, acc.y);
        acc.z = fmaf(b.z, w4.z, acc.z);
        acc.w = fmaf(b.w, w4.w, acc.w);
    }

    __stcs((float4*)(out + (size_t)bc * HW + (size_t)y * W + x0), acc);
}

extern "C" void kernel_launch(void* const* d_in, const int* in_sizes, int n_in,
                              void* d_out, int out_size)
{
    const float* x    = (const float*)d_in[0];   // (4,32,256,256)
    const float* kern = (const float*)d_in[1];   // (4,800,256,256)
    // d_in[2] = kernel_size (int scalar) — fixed at 5, compiled in.
    float* out = (float*)d_out;

    dim3 grid(H / 8, 4 * 32);   // 32 row-groups x 128 (b,c) slices
    kpconv_kernel<<<grid, 512>>>(x, kern, out);
}

// round 16
// speedup vs baseline: 1.0267x; 1.0047x over previous
#include <cuda_runtime.h>
#include <cstdint>

// Problem constants (fixed shapes from reference setup_inputs):
// x:      (B=4, C=32, H=256, W=256) fp32
// kernel: (B=4, C*K*K=800, H=256, W=256) fp32, channel = c*25 + i*5 + j
// out:    same shape as x
// out[b,c,y,x] = sum_{i,j} x_edgepad[b,c,y+i-2,x+j-2] * kernel[b,(c*5+i)*5+j,y,x]
//
// Pure HBM stream (kernel tensor = 839 MB read once, zero reuse).
// Empirical bracketing so far:
//   rows/CTA {4:125.1, 8:123.4, 16:125.7} us -> 8
//   regs {32-forced:129.5, 38-natural:123.0} us -> per-warp MLP beats occupancy
// R16 lever: software-pipeline tap loads one i-iteration ahead (10 LDG.128
// in flight per warp instead of 5) + hoist first batch above the staging
// barrier. Trades occupancy (3->2 CTAs/SM) for +33% in-flight bytes.

constexpr int H  = 256;
constexpr int W  = 256;
constexpr int HW = H * W;
constexpr int KK = 25;

__global__ void __launch_bounds__(512)
kpconv_kernel(const float* __restrict__ x,
              const float* __restrict__ kern,
              float* __restrict__ out)
{
    __shared__ __align__(16) float s[12][264];

    const int yg = blockIdx.x;            // 0..31  (row group)
    const int bc = blockIdx.y;            // 0..127 (b*C + c)
    const int y0 = yg << 3;               // first output row of this block
    const int t  = threadIdx.x;

    const float* xsl = x + (size_t)bc * HW;   // this (b,c) slice of x

    // Compute-phase coordinates (needed early for the hoisted tap prefetch).
    const int ry = t >> 6;                 // 0..7  output row within group
    const int x0 = (t & 63) << 2;          // 0..252 output col (float4 aligned)
    const int y  = y0 + ry;
    const float* kb = kern + (size_t)bc * KK * HW + (size_t)y * W + x0;

    // ---- Prefetch tap batch for i=0 BEFORE the staging barrier ----
    // These loads depend only on gmem; their DRAM latency hides behind the
    // smem staging + __syncthreads below.
    float4 w0 = __ldcs((const float4*)(kb + 0 * HW));
    float4 w1 = __ldcs((const float4*)(kb + 1 * HW));
    float4 w2 = __ldcs((const float4*)(kb + 2 * HW));
    float4 w3 = __ldcs((const float4*)(kb + 3 * HW));
    float4 w4 = __ldcs((const float4*)(kb + 4 * HW));

    // ---- Stage x tile into shared memory (with edge replication) ----
    // Tile: 12 rows (8 output + 2 halo each side) x 264 cols.
    //   cols [0,1] = left edge repl, [2..257] = data, [258,259] = right repl.
    // Interior stores are 8B-aligned (offset 8 mod 16) -> two float2 stores.
    {
        #pragma unroll
        for (int rep = 0; rep < 2; ++rep) {
            int idx = t + rep * 512;
            if (idx < 12 * 64) {
                int sy = idx >> 6;                       // 0..11
                int q  = idx & 63;                       // 0..63
                int gy = y0 + sy - 2;
                gy = gy < 0 ? 0 : (gy > H - 1 ? H - 1 : gy);
                float4 v = __ldg((const float4*)(xsl + gy * W + (q << 2)));
                float* dst = &s[sy][2 + (q << 2)];
                *(float2*)(dst)     = make_float2(v.x, v.y);
                *(float2*)(dst + 2) = make_float2(v.z, v.w);
            }
        }
        if (t < 48) {
            int sy = t >> 2;                             // 0..11
            int e  = t & 3;
            int gy = y0 + sy - 2;
            gy = gy < 0 ? 0 : (gy > H - 1 ? H - 1 : gy);
            if (e < 2) s[sy][e]           = xsl[gy * W];          // cols -2,-1
            else       s[sy][258 + (e-2)] = xsl[gy * W + W - 1];  // cols 256,257
        }
    }
    __syncthreads();

    float4 acc = make_float4(0.f, 0.f, 0.f, 0.f);

    #pragma unroll
    for (int i = 0; i < 5; ++i) {
        // Prefetch next iteration's tap batch (independent of this one's
        // FMAs) -> up to 10 LDG.128 in flight per thread.
        float4 n0, n1, n2, n3, n4;
        if (i < 4) {
            const float* kn = kb + (size_t)(i + 1) * 5 * HW;
            n0 = __ldcs((const float4*)(kn + 0 * HW));
            n1 = __ldcs((const float4*)(kn + 1 * HW));
            n2 = __ldcs((const float4*)(kn + 2 * HW));
            n3 = __ldcs((const float4*)(kn + 3 * HW));
            n4 = __ldcs((const float4*)(kn + 4 * HW));
        }

        // x window: smem cols x0..x0+7 of row (ry+i). 16B-aligned reads.
        const float4 a = *(const float4*)&s[ry + i][x0];
        const float4 b = *(const float4*)&s[ry + i][x0 + 4];

        // j = 0: window a.x..a.w
        acc.x = fmaf(a.x, w0.x, acc.x);
        acc.y = fmaf(a.y, w0.y, acc.y);
        acc.z = fmaf(a.z, w0.z, acc.z);
        acc.w = fmaf(a.w, w0.w, acc.w);
        // j = 1: a.y..b.x
        acc.x = fmaf(a.y, w1.x, acc.x);
        acc.y = fmaf(a.z, w1.y, acc.y);
        acc.z = fmaf(a.w, w1.z, acc.z);
        acc.w = fmaf(b.x, w1.w, acc.w);
        // j = 2: a.z..b.y
        acc.x = fmaf(a.z, w2.x, acc.x);
        acc.y = fmaf(a.w, w2.y, acc.y);
        acc.z = fmaf(b.x, w2.z, acc.z);
        acc.w = fmaf(b.y, w2.w, acc.w);
        // j = 3: a.w..b.z
        acc.x = fmaf(a.w, w3.x, acc.x);
        acc.y = fmaf(b.x, w3.y, acc.y);
        acc.z = fmaf(b.y, w3.z, acc.z);
        acc.w = fmaf(b.z, w3.w, acc.w);
        // j = 4: b.x..b.w
        acc.x = fmaf(b.x, w4.x, acc.x);
        acc.y = fmaf(b.y, w4.y, acc.y);
        acc.z = fmaf(b.z, w4.z, acc.z);
        acc.w = fmaf(b.w, w4.w, acc.w);

        if (i < 4) { w0 = n0; w1 = n1; w2 = n2; w3 = n3; w4 = n4; }
    }

    __stcs((float4*)(out + (size_t)bc * HW + (size_t)y * W + x0), acc);
}

extern "C" void kernel_launch(void* const* d_in, const int* in_sizes, int n_in,
                              void* d_out, int out_size)
{
    const float* x    = (const float*)d_in[0];   // (4,32,256,256)
    const float* kern = (const float*)d_in[1];   // (4,800,256,256)
    // d_in[2] = kernel_size (int scalar) — fixed at 5, compiled in.
    float* out = (float*)d_out;

    dim3 grid(H / 8, 4 * 32);   // 32 row-groups x 128 (b,c) slices
    kpconv_kernel<<<grid, 512>>>(x, kern, out);
}

// round 17
// speedup vs baseline: 1.0337x; 1.0068x over previous
#include <cuda_runtime.h>
#include <cstdint>

// Problem constants (fixed shapes from reference setup_inputs):
// x:      (B=4, C=32, H=256, W=256) fp32
// kernel: (B=4, C*K*K=800, H=256, W=256) fp32, channel = c*25 + i*5 + j
// out:    same shape as x
// out[b,c,y,x] = sum_{i,j} x_edgepad[b,c,y+i-2,x+j-2] * kernel[b,(c*5+i)*5+j,y,x]
//
// Pure HBM stream (kernel tensor = 839 MB read once, zero reuse).
// Empirical bracketing so far:
//   rows/CTA {4:125.1, 8:123.4, 16:125.7} us -> 8
//   regs {32-forced:129.5, 38-natural:123.0} us -> per-warp MLP beats occupancy
// R16 lever: software-pipeline tap loads one i-iteration ahead (10 LDG.128
// in flight per warp instead of 5) + hoist first batch above the staging
// barrier. Trades occupancy (3->2 CTAs/SM) for +33% in-flight bytes.

constexpr int H  = 256;
constexpr int W  = 256;
constexpr int HW = H * W;
constexpr int KK = 25;

__global__ void __launch_bounds__(512)
kpconv_kernel(const float* __restrict__ x,
              const float* __restrict__ kern,
              float* __restrict__ out)
{
    __shared__ __align__(16) float s[12][264];

    const int yg = blockIdx.x;            // 0..31  (row group)
    const int bc = blockIdx.y;            // 0..127 (b*C + c)
    const int y0 = yg << 3;               // first output row of this block
    const int t  = threadIdx.x;

    const float* xsl = x + (size_t)bc * HW;   // this (b,c) slice of x

    // Compute-phase coordinates (needed early for the hoisted tap prefetch).
    const int ry = t >> 6;                 // 0..7  output row within group
    const int x0 = (t & 63) << 2;          // 0..252 output col (float4 aligned)
    const int y  = y0 + ry;
    const float* kb = kern + (size_t)bc * KK * HW + (size_t)y * W + x0;

    // ---- Prefetch tap batch for i=0 BEFORE the staging barrier ----
    // These loads depend only on gmem; their DRAM latency hides behind the
    // smem staging + __syncthreads below.
    float4 w0 = __ldcs((const float4*)(kb + 0 * HW));
    float4 w1 = __ldcs((const float4*)(kb + 1 * HW));
    float4 w2 = __ldcs((const float4*)(kb + 2 * HW));
    float4 w3 = __ldcs((const float4*)(kb + 3 * HW));
    float4 w4 = __ldcs((const float4*)(kb + 4 * HW));

    // ---- Stage x tile into shared memory (with edge replication) ----
    // Tile: 12 rows (8 output + 2 halo each side) x 264 cols.
    //   cols [0,1] = left edge repl, [2..257] = data, [258,259] = right repl.
    // Interior stores are 8B-aligned (offset 8 mod 16) -> two float2 stores.
    {
        #pragma unroll
        for (int rep = 0; rep < 2; ++rep) {
            int idx = t + rep * 512;
            if (idx < 12 * 64) {
                int sy = idx >> 6;                       // 0..11
                int q  = idx & 63;                       // 0..63
                int gy = y0 + sy - 2;
                gy = gy < 0 ? 0 : (gy > H - 1 ? H - 1 : gy);
                float4 v = __ldg((const float4*)(xsl + gy * W + (q << 2)));
                float* dst = &s[sy][2 + (q << 2)];
                *(float2*)(dst)     = make_float2(v.x, v.y);
                *(float2*)(dst + 2) = make_float2(v.z, v.w);
            }
        }
        if (t < 48) {
            int sy = t >> 2;                             // 0..11
            int e  = t & 3;
            int gy = y0 + sy - 2;
            gy = gy < 0 ? 0 : (gy > H - 1 ? H - 1 : gy);
            if (e < 2) s[sy][e]           = xsl[gy * W];          // cols -2,-1
            else       s[sy][258 + (e-2)] = xsl[gy * W + W - 1];  // cols 256,257
        }
    }
    __syncthreads();

    float4 acc = make_float4(0.f, 0.f, 0.f, 0.f);

    #pragma unroll
    for (int i = 0; i < 5; ++i) {
        // Prefetch next iteration's tap batch (independent of this one's
        // FMAs) -> up to 10 LDG.128 in flight per thread.
        float4 n0, n1, n2, n3, n4;
        if (i < 4) {
            const float* kn = kb + (size_t)(i + 1) * 5 * HW;
            n0 = __ldcs((const float4*)(kn + 0 * HW));
            n1 = __ldcs((const float4*)(kn + 1 * HW));
            n2 = __ldcs((const float4*)(kn + 2 * HW));
            n3 = __ldcs((const float4*)(kn + 3 * HW));
            n4 = __ldcs((const float4*)(kn + 4 * HW));
        }

        // x window: smem cols x0..x0+7 of row (ry+i). 16B-aligned reads.
        const float4 a = *(const float4*)&s[ry + i][x0];
        const float4 b = *(const float4*)&s[ry + i][x0 + 4];

        // j = 0: window a.x..a.w
        acc.x = fmaf(a.x, w0.x, acc.x);
        acc.y = fmaf(a.y, w0.y, acc.y);
        acc.z = fmaf(a.z, w0.z, acc.z);
        acc.w = fmaf(a.w, w0.w, acc.w);
        // j = 1: a.y..b.x
        acc.x = fmaf(a.y, w1.x, acc.x);
        acc.y = fmaf(a.z, w1.y, acc.y);
        acc.z = fmaf(a.w, w1.z, acc.z);
        acc.w = fmaf(b.x, w1.w, acc.w);
        // j = 2: a.z..b.y
        acc.x = fmaf(a.z, w2.x, acc.x);
        acc.y = fmaf(a.w, w2.y, acc.y);
        acc.z = fmaf(b.x, w2.z, acc.z);
        acc.w = fmaf(b.y, w2.w, acc.w);
        // j = 3: a.w..b.z
        acc.x = fmaf(a.w, w3.x, acc.x);
        acc.y = fmaf(b.x, w3.y, acc.y);
        acc.z = fmaf(b.y, w3.z, acc.z);
        acc.w = fmaf(b.z, w3.w, acc.w);
        // j = 4: b.x..b.w
        acc.x = fmaf(b.x, w4.x, acc.x);
        acc.y = fmaf(b.y, w4.y, acc.y);
        acc.z = fmaf(b.z, w4.z, acc.z);
        acc.w = fmaf(b.w, w4.w, acc.w);

        if (i < 4) { w0 = n0; w1 = n1; w2 = n2; w3 = n3; w4 = n4; }
    }

    __stcs((float4*)(out + (size_t)bc * HW + (size_t)y * W + x0), acc);
}

extern "C" void kernel_launch(void* const* d_in, const int* in_sizes, int n_in,
                              void* d_out, int out_size)
{
    const float* x    = (const float*)d_in[0];   // (4,32,256,256)
    const float* kern = (const float*)d_in[1];   // (4,800,256,256)
    // d_in[2] = kernel_size (int scalar) — fixed at 5, compiled in.
    float* out = (float*)d_out;

    dim3 grid(H / 8, 4 * 32);   // 32 row-groups x 128 (b,c) slices
    kpconv_kernel<<<grid, 512>>>(x, kern, out);
}